// round 1
// baseline (speedup 1.0000x reference)
#include <cuda_runtime.h>

// out = IFFT( D .* FFT( A .* x ) ) per row, C = 4096, complex stored as (re, im) float pairs.
// A and D scale re/im independently (elementwise, NOT complex multiply).
// One CTA of 256 threads per row; 4096 = 16*16*16 radix-16 register FFT,
// two SoA shared-memory transposes per direction, conflict-free strides 273 / 17.

#define REV(c) ((((c) & 3) << 2) | ((c) >> 2))

__device__ __forceinline__ float2 cadd(float2 a, float2 b){ return make_float2(a.x + b.x, a.y + b.y); }
__device__ __forceinline__ float2 csub(float2 a, float2 b){ return make_float2(a.x - b.x, a.y - b.y); }
__device__ __forceinline__ float2 cmul(float2 a, float2 b){
    return make_float2(fmaf(a.x, b.x, -(a.y * b.y)), fmaf(a.x, b.y, a.y * b.x));
}

// multiply by omega_4 = -i (forward, DIR=-1) or +i (inverse, DIR=+1)
template<int DIR> __device__ __forceinline__ float2 mulj(float2 a){
    return (DIR < 0) ? make_float2(a.y, -a.x) : make_float2(-a.y, a.x);
}

// In-place 4-point DFT: y[c] = sum_a x[a] w4^{a c}, w4 = e^{DIR*2pi i/4}
template<int DIR>
__device__ __forceinline__ void fft4(float2& x0, float2& x1, float2& x2, float2& x3){
    float2 t0 = cadd(x0, x2), t1 = csub(x0, x2);
    float2 t2 = cadd(x1, x3), t3 = mulj<DIR>(csub(x1, x3));
    x0 = cadd(t0, t2); x2 = csub(t0, t2);
    x1 = cadd(t1, t3); x3 = csub(t1, t3);
}

// Twiddle constant: forward value (c_, s_); inverse = conjugate
template<int DIR> __device__ __forceinline__ float2 TW(float c_, float s_){
    return make_float2(c_, (DIR < 0) ? s_ : -s_);
}

#define TC1 0.92387953251128674f
#define TS1 0.38268343236508978f
#define TC2 0.70710678118654752f

// 16-point DFT, input in natural slots (slot a = logical a), output at slot REV(c).
template<int DIR>
__device__ __forceinline__ void fft16_nat(float2 v[16]){
    // inner FFT4 over a1 (stride 4), fixed a0 -> T[a0][c0] at slot a0 + 4*c0
    fft4<DIR>(v[0], v[4], v[8],  v[12]);
    fft4<DIR>(v[1], v[5], v[9],  v[13]);
    fft4<DIR>(v[2], v[6], v[10], v[14]);
    fft4<DIR>(v[3], v[7], v[11], v[15]);
    // twiddle w16^{a0*c0} at slot a0 + 4*c0
    v[5]  = cmul(v[5],  TW<DIR>( TC1, -TS1));  // m=1
    v[9]  = cmul(v[9],  TW<DIR>( TC2, -TC2));  // m=2
    v[13] = cmul(v[13], TW<DIR>( TS1, -TC1));  // m=3
    v[6]  = cmul(v[6],  TW<DIR>( TC2, -TC2));  // m=2
    v[10] = cmul(v[10], TW<DIR>( 0.f, -1.f));  // m=4
    v[14] = cmul(v[14], TW<DIR>(-TC2, -TC2));  // m=6
    v[7]  = cmul(v[7],  TW<DIR>( TS1, -TC1));  // m=3
    v[11] = cmul(v[11], TW<DIR>(-TC2, -TC2));  // m=6
    v[15] = cmul(v[15], TW<DIR>(-TC1,  TS1));  // m=9
    // outer FFT4 over a0 (contiguous quads); out[c0+4c1] lands at slot 4*c0 + c1 = REV
    fft4<DIR>(v[0],  v[1],  v[2],  v[3]);
    fft4<DIR>(v[4],  v[5],  v[6],  v[7]);
    fft4<DIR>(v[8],  v[9],  v[10], v[11]);
    fft4<DIR>(v[12], v[13], v[14], v[15]);
}

// 16-point DFT, input with logical index a at slot REV(a); output in natural slots.
template<int DIR>
__device__ __forceinline__ void fft16_rev(float2 v[16]){
    // inner FFT4 over a1: slots 4*a0 + a1 (contiguous)
    fft4<DIR>(v[0],  v[1],  v[2],  v[3]);
    fft4<DIR>(v[4],  v[5],  v[6],  v[7]);
    fft4<DIR>(v[8],  v[9],  v[10], v[11]);
    fft4<DIR>(v[12], v[13], v[14], v[15]);
    // twiddle w16^{a0*c0} at slot 4*a0 + c0
    v[5]  = cmul(v[5],  TW<DIR>( TC1, -TS1));  // m=1
    v[6]  = cmul(v[6],  TW<DIR>( TC2, -TC2));  // m=2
    v[7]  = cmul(v[7],  TW<DIR>( TS1, -TC1));  // m=3
    v[9]  = cmul(v[9],  TW<DIR>( TC2, -TC2));  // m=2
    v[10] = cmul(v[10], TW<DIR>( 0.f, -1.f));  // m=4
    v[11] = cmul(v[11], TW<DIR>(-TC2, -TC2));  // m=6
    v[13] = cmul(v[13], TW<DIR>( TS1, -TC1));  // m=3
    v[14] = cmul(v[14], TW<DIR>(-TC2, -TC2));  // m=6
    v[15] = cmul(v[15], TW<DIR>(-TC1,  TS1));  // m=9
    // outer FFT4 over a0 (stride 4); out[c0+4c1] at slot 4*c1 + c0 = natural (c0+4c1)
    fft4<DIR>(v[0], v[4], v[8],  v[12]);
    fft4<DIR>(v[1], v[5], v[9],  v[13]);
    fft4<DIR>(v[2], v[6], v[10], v[14]);
    fft4<DIR>(v[3], v[7], v[11], v[15]);
}

// Apply w^k (w = e^{DIR*i*theta}) to v[slot(k)], k = 1..15. RV selects REV slot mapping.
template<int DIR, int RV>
__device__ __forceinline__ void twiddle_stage(float2 v[16], float theta){
    float sn, cs;
    __sincosf(theta, &sn, &cs);
    float2 w  = make_float2(cs, (DIR < 0) ? -sn : sn);
    float2 w2 = cmul(w, w);
    float2 po = w, pe = w2;      // odd / even power chains (shorter dep chain)
    #pragma unroll
    for (int k = 1; k < 16; ++k){
        const int slot = RV ? REV(k) : k;
        if (k & 1){
            v[slot] = cmul(v[slot], po);
            if (k + 2 < 16) po = cmul(po, w2);
        } else {
            v[slot] = cmul(v[slot], pe);
            if (k + 2 < 16) pe = cmul(pe, w2);
        }
    }
}

#define S1STRIDE 273   // 256 + 17 ; 273 mod 32 = 17 -> conflict-free exchange 1
#define S2STRIDE 17    // 16 + 1   ; 17 is self-inverse mod 32 -> conflict-free exchange 2

__global__ void __launch_bounds__(256) afdf_fft_kernel(
    const float2* __restrict__ x,
    const float2* __restrict__ A,
    const float2* __restrict__ D,
    float2* __restrict__ out)
{
    __shared__ float s_re[16 * S1STRIDE];   // 4368 floats, also reused as [256][17]
    __shared__ float s_im[16 * S1STRIDE];

    const int t    = threadIdx.x;      // = b index (0..255)
    const int c_lo = t & 15;
    const int b2   = t >> 4;
    const size_t base = (size_t)blockIdx.x * 4096;

    float2 v[16];

    // ---- load + A scale (elementwise re/im) ----
    #pragma unroll
    for (int a = 0; a < 16; ++a){
        const int n = t + 256 * a;
        const float2 xv = x[base + n];
        const float2 av = A[n];
        v[a] = make_float2(xv.x * av.x, xv.y * av.y);
    }

    // ================= forward FFT =================
    fft16_nat<-1>(v);                                           // U[c] at REV(c)
    twiddle_stage<-1, 1>(v, (float)t * 1.5339807878856412e-3f); // * w4096^{t c}
    #pragma unroll
    for (int c = 0; c < 16; ++c){
        const float2 z = v[REV(c)];
        s_re[c * S1STRIDE + t] = z.x;  s_im[c * S1STRIDE + t] = z.y;
    }
    __syncthreads();
    #pragma unroll
    for (int a2 = 0; a2 < 16; ++a2){
        const int idx = c_lo * S1STRIDE + 16 * a2 + b2;
        v[a2] = make_float2(s_re[idx], s_im[idx]);
    }
    fft16_nat<-1>(v);
    twiddle_stage<-1, 1>(v, (float)b2 * 2.4543692606170259e-2f); // * w256^{b2 c2}
    __syncthreads();
    #pragma unroll
    for (int c2 = 0; c2 < 16; ++c2){
        const float2 z = v[REV(c2)];
        const int idx = (c2 * 16 + c_lo) * S2STRIDE + b2;
        s_re[idx] = z.x;  s_im[idx] = z.y;
    }
    __syncthreads();
    #pragma unroll
    for (int b = 0; b < 16; ++b){
        const int idx = t * S2STRIDE + b;
        v[b] = make_float2(s_re[idx], s_im[idx]);
    }
    fft16_nat<-1>(v);
    // now F[256*d2 + t] sits at v[REV(d2)]

    // ================= D scale (1/N folded) =================
    #pragma unroll
    for (int d2 = 0; d2 < 16; ++d2){
        const float2 dv = D[t + 256 * d2];
        float2 z = v[REV(d2)];
        z.x *= dv.x * (1.0f / 4096.0f);
        z.y *= dv.y * (1.0f / 4096.0f);
        v[REV(d2)] = z;
    }
    __syncthreads();   // protect shared reuse across directions

    // ================= inverse FFT =================
    fft16_rev<1>(v);                                            // input at REV slots -> natural out
    twiddle_stage<1, 0>(v, (float)t * 1.5339807878856412e-3f);
    #pragma unroll
    for (int c = 0; c < 16; ++c){
        const float2 z = v[c];
        s_re[c * S1STRIDE + t] = z.x;  s_im[c * S1STRIDE + t] = z.y;
    }
    __syncthreads();
    #pragma unroll
    for (int a2 = 0; a2 < 16; ++a2){
        const int idx = c_lo * S1STRIDE + 16 * a2 + b2;
        v[a2] = make_float2(s_re[idx], s_im[idx]);
    }
    fft16_nat<1>(v);
    twiddle_stage<1, 1>(v, (float)b2 * 2.4543692606170259e-2f);
    __syncthreads();
    #pragma unroll
    for (int c2 = 0; c2 < 16; ++c2){
        const float2 z = v[REV(c2)];
        const int idx = (c2 * 16 + c_lo) * S2STRIDE + b2;
        s_re[idx] = z.x;  s_im[idx] = z.y;
    }
    __syncthreads();
    #pragma unroll
    for (int b = 0; b < 16; ++b){
        const int idx = t * S2STRIDE + b;
        v[b] = make_float2(s_re[idx], s_im[idx]);
    }
    fft16_nat<1>(v);

    // ---- store: out[256*d2 + t] at v[REV(d2)] ----
    #pragma unroll
    for (int d2 = 0; d2 < 16; ++d2){
        out[base + t + 256 * d2] = v[REV(d2)];
    }
}

extern "C" void kernel_launch(void* const* d_in, const int* in_sizes, int n_in,
                              void* d_out, int out_size)
{
    const float2* x = (const float2*)d_in[0];
    const float2* A = (const float2*)d_in[1];
    const float2* D = (const float2*)d_in[2];
    float2* out = (float2*)d_out;

    const int rows = in_sizes[0] / (4096 * 2);   // floats per row = C*2
    afdf_fft_kernel<<<rows, 256>>>(x, A, D, out);
}

// round 2
// speedup vs baseline: 1.2402x; 1.2402x over previous
#include <cuda_runtime.h>
#include <cstdint>

// out = IFFT( D .* FFT( A .* x ) ) per row, C = 4096, complex as (re,im) float pairs.
// A, D scale re/im independently (elementwise).
//
// 128 threads per row. Each thread processes TWO sub-FFT lanes packed into
// f32x2 (64-bit) registers; all butterflies/twiddles use packed PTX
// add/sub/mul/fma .f32x2 (FFMA2 on sm_103a) -> half the fp32 instructions.
// 4096 = 16^3: three radix-16 register stages, two 64-bit shared exchanges
// per direction, all access patterns conflict-free for 8B accesses.

typedef unsigned long long ull;

#define REV(c) ((((c) & 3) << 2) | ((c) >> 2))

// ---------------- packed f32x2 primitives ----------------
__device__ __forceinline__ ull pk(float a, float b){
    ull r; asm("mov.b64 %0, {%1, %2};" : "=l"(r) : "f"(a), "f"(b)); return r;
}
__device__ __forceinline__ void unpk(ull v, float& a, float& b){
    asm("mov.b64 {%0, %1}, %2;" : "=f"(a), "=f"(b) : "l"(v));
}
__device__ __forceinline__ float plo(ull v){ float a,b; unpk(v,a,b); return a; }
__device__ __forceinline__ float phi(ull v){ float a,b; unpk(v,a,b); return b; }
__device__ __forceinline__ ull padd(ull a, ull b){
    ull r; asm("add.rn.f32x2 %0, %1, %2;" : "=l"(r) : "l"(a), "l"(b)); return r;
}
__device__ __forceinline__ ull psub(ull a, ull b){
    ull r; asm("sub.rn.f32x2 %0, %1, %2;" : "=l"(r) : "l"(a), "l"(b)); return r;
}
__device__ __forceinline__ ull pmul(ull a, ull b){
    ull r; asm("mul.rn.f32x2 %0, %1, %2;" : "=l"(r) : "l"(a), "l"(b)); return r;
}
__device__ __forceinline__ ull pfma(ull a, ull b, ull c){
    ull r; asm("fma.rn.f32x2 %0, %1, %2, %3;" : "=l"(r) : "l"(a), "l"(b), "l"(c)); return r;
}
__device__ __forceinline__ ull pneg(ull a){   // flip both sign bits (ALU pipe, not FMA)
    ull r; asm("xor.b64 %0, %1, %2;" : "=l"(r) : "l"(a), "l"(0x8000000080000000ULL)); return r;
}
// pull the two low / two high floats of (A,B) into packed regs
__device__ __forceinline__ ull pklo(ull A, ull B){ return pk(plo(A), plo(B)); }
__device__ __forceinline__ ull pkhi(ull A, ull B){ return pk(phi(A), phi(B)); }

// packed complex multiply: (r,i) *= (wr,wi)
__device__ __forceinline__ void cmulp(ull& r, ull& i, ull wr, ull wi){
    ull t  = pmul(i, wi);
    ull nr = psub(pmul(r, wr), t);
    ull ni = pfma(r, wi, pmul(i, wr));
    r = nr; i = ni;
}
// multiply by -i (DIR<0) / +i (DIR>0)
template<int DIR> __device__ __forceinline__ void muljp(ull& r, ull& i){
    ull t = r;
    if (DIR < 0){ r = i;       i = pneg(t); }
    else        { r = pneg(i); i = t; }
}
// constant twiddle, forward (cr, ci_f); inverse = conjugate
template<int DIR> __device__ __forceinline__ void cmulc(ull& r, ull& i, float cr, float ci_f){
    const float ci = (DIR < 0) ? ci_f : -ci_f;
    cmulp(r, i, pk(cr, cr), pk(ci, ci));
}

#define TC1 0.92387953251128674f
#define TS1 0.38268343236508978f
#define TC2 0.70710678118654752f

// packed radix-4 butterfly (two lanes at once)
template<int DIR>
__device__ __forceinline__ void fft4p(ull& r0, ull& i0, ull& r1, ull& i1,
                                      ull& r2, ull& i2, ull& r3, ull& i3){
    ull t0r = padd(r0, r2), t0i = padd(i0, i2);
    ull t1r = psub(r0, r2), t1i = psub(i0, i2);
    ull t2r = padd(r1, r3), t2i = padd(i1, i3);
    ull t3r, t3i;
    if (DIR < 0){ t3r = psub(i1, i3); t3i = psub(r3, r1); }
    else        { t3r = psub(i3, i1); t3i = psub(r1, r3); }
    r0 = padd(t0r, t2r); i0 = padd(t0i, t2i);
    r2 = psub(t0r, t2r); i2 = psub(t0i, t2i);
    r1 = padd(t1r, t3r); i1 = padd(t1i, t3i);
    r3 = psub(t1r, t3r); i3 = psub(t1i, t3i);
}

// 16-point DFT, natural slots in -> output c at slot REV(c)
template<int DIR>
__device__ __forceinline__ void fft16_nat_p(ull re[16], ull im[16]){
    fft4p<DIR>(re[0],im[0], re[4],im[4], re[8], im[8],  re[12],im[12]);
    fft4p<DIR>(re[1],im[1], re[5],im[5], re[9], im[9],  re[13],im[13]);
    fft4p<DIR>(re[2],im[2], re[6],im[6], re[10],im[10], re[14],im[14]);
    fft4p<DIR>(re[3],im[3], re[7],im[7], re[11],im[11], re[15],im[15]);
    cmulc<DIR>(re[5], im[5],  TC1, -TS1);
    cmulc<DIR>(re[9], im[9],  TC2, -TC2);
    cmulc<DIR>(re[13],im[13], TS1, -TC1);
    cmulc<DIR>(re[6], im[6],  TC2, -TC2);
    muljp<DIR>(re[10],im[10]);
    cmulc<DIR>(re[14],im[14],-TC2, -TC2);
    cmulc<DIR>(re[7], im[7],  TS1, -TC1);
    cmulc<DIR>(re[11],im[11],-TC2, -TC2);
    cmulc<DIR>(re[15],im[15],-TC1,  TS1);
    fft4p<DIR>(re[0], im[0],  re[1], im[1],  re[2], im[2],  re[3], im[3]);
    fft4p<DIR>(re[4], im[4],  re[5], im[5],  re[6], im[6],  re[7], im[7]);
    fft4p<DIR>(re[8], im[8],  re[9], im[9],  re[10],im[10], re[11],im[11]);
    fft4p<DIR>(re[12],im[12], re[13],im[13], re[14],im[14], re[15],im[15]);
}

// 16-point DFT, input logical a at slot REV(a) -> natural output slots
template<int DIR>
__device__ __forceinline__ void fft16_rev_p(ull re[16], ull im[16]){
    fft4p<DIR>(re[0], im[0],  re[1], im[1],  re[2], im[2],  re[3], im[3]);
    fft4p<DIR>(re[4], im[4],  re[5], im[5],  re[6], im[6],  re[7], im[7]);
    fft4p<DIR>(re[8], im[8],  re[9], im[9],  re[10],im[10], re[11],im[11]);
    fft4p<DIR>(re[12],im[12], re[13],im[13], re[14],im[14], re[15],im[15]);
    cmulc<DIR>(re[5], im[5],  TC1, -TS1);
    cmulc<DIR>(re[6], im[6],  TC2, -TC2);
    cmulc<DIR>(re[7], im[7],  TS1, -TC1);
    cmulc<DIR>(re[9], im[9],  TC2, -TC2);
    muljp<DIR>(re[10],im[10]);
    cmulc<DIR>(re[11],im[11],-TC2, -TC2);
    cmulc<DIR>(re[13],im[13], TS1, -TC1);
    cmulc<DIR>(re[14],im[14],-TC2, -TC2);
    cmulc<DIR>(re[15],im[15],-TC1,  TS1);
    fft4p<DIR>(re[0],im[0], re[4],im[4], re[8], im[8],  re[12],im[12]);
    fft4p<DIR>(re[1],im[1], re[5],im[5], re[9], im[9],  re[13],im[13]);
    fft4p<DIR>(re[2],im[2], re[6],im[6], re[10],im[10], re[14],im[14]);
    fft4p<DIR>(re[3],im[3], re[7],im[7], re[11],im[11], re[15],im[15]);
}

// apply w^k to v[slot(k)], k=1..15; w = e^{DIR*i*theta_lane} (two lanes)
template<int DIR, int RV>
__device__ __forceinline__ void twiddle_stage_p(ull re[16], ull im[16], float th0, float th1){
    float s0, c0, s1, c1;
    __sincosf(th0, &s0, &c0);
    __sincosf(th1, &s1, &c1);
    if (DIR < 0){ s0 = -s0; s1 = -s1; }
    ull wr = pk(c0, c1), wi = pk(s0, s1);
    ull w2r = psub(pmul(wr, wr), pmul(wi, wi));
    ull w2i = padd(pmul(wr, wi), pmul(wi, wr));
    ull por = wr,  poi = wi;   // odd powers
    ull per = w2r, pei = w2i;  // even powers
    #pragma unroll
    for (int k = 1; k < 16; ++k){
        const int slot = RV ? REV(k) : k;
        if (k & 1){
            cmulp(re[slot], im[slot], por, poi);
            if (k + 2 < 16) cmulp(por, poi, w2r, w2i);
        } else {
            cmulp(re[slot], im[slot], per, pei);
            if (k + 2 < 16) cmulp(per, pei, w2r, w2i);
        }
    }
}

#define S1R 129   // pair-row stride (8B units); 129 mod 16 = 1 -> conflict-free
#define S2R 9     // 9 coprime 16 -> conflict-free
#define D4096 1.5339807878856412e-3f   // 2*pi/4096
#define D256  2.4543692606170259e-2f   // 2*pi/256
#define INV_N (1.0f / 4096.0f)

__global__ void __launch_bounds__(128) afdf_fft2_kernel(
    const float4* __restrict__ x4,
    const float4* __restrict__ A4,
    const float2* __restrict__ D2,
    float2* __restrict__ out2)
{
    // shared scratch, reused: S1 = 16 rows x 129 pairs; S2 = 256 rows x 9 pairs
    __shared__ ull sbuf[2 * 256 * S2R];          // 4608 ull = 36,864 B
    ull* const s1re = sbuf;  ull* const s1im = sbuf + 16 * S1R;   // 2064
    ull* const s2re = sbuf;  ull* const s2im = sbuf + 256 * S2R;  // 2304

    const int t  = threadIdx.x;        // 0..127
    const int c1 = t & 15;
    const int u  = t >> 4;             // 0..7
    const size_t rb4 = (size_t)blockIdx.x * 2048;   // row base in float4 units
    const size_t rb2 = (size_t)blockIdx.x * 4096;   // row base in float2 units

    ull re[16], im[16];

    // ---- load x, apply A; lanes = points m=(2t, 2t+1) ----
    #pragma unroll
    for (int a = 0; a < 16; ++a){
        const float4 xv = x4[rb4 + 128 * a + t];
        const float4 av = A4[128 * a + t];
        re[a] = pmul(pk(xv.x, xv.z), pk(av.x, av.z));
        im[a] = pmul(pk(xv.y, xv.w), pk(av.y, av.w));
    }

    // ================= forward =================
    fft16_nat_p<-1>(re, im);
    twiddle_stage_p<-1, 1>(re, im, (float)(2*t) * D4096, (float)(2*t + 1) * D4096);
    #pragma unroll
    for (int c = 0; c < 16; ++c){
        s1re[c * S1R + t] = re[REV(c)];
        s1im[c * S1R + t] = im[REV(c)];
    }
    __syncthreads();
    // stage 2: lanes = (b2 = 2u, 2u+1), iterate a2 (m = 16*a2 + b2)
    #pragma unroll
    for (int a2 = 0; a2 < 16; ++a2){
        re[a2] = s1re[c1 * S1R + 8 * a2 + u];
        im[a2] = s1im[c1 * S1R + 8 * a2 + u];
    }
    fft16_nat_p<-1>(re, im);
    twiddle_stage_p<-1, 1>(re, im, (float)(2*u) * D256, (float)(2*u + 1) * D256);
    __syncthreads();
    #pragma unroll
    for (int c2 = 0; c2 < 16; ++c2){
        const int r = 16 * c2 + c1;
        s2re[r * S2R + u] = re[REV(c2)];
        s2im[r * S2R + u] = im[REV(c2)];
    }
    __syncthreads();
    // stage 3: lanes = (r = t, t+128); stored pairs are along b2 -> repack
    #pragma unroll
    for (int uu = 0; uu < 8; ++uu){
        const ull Lr = s2re[t * S2R + uu],        Li = s2im[t * S2R + uu];
        const ull Hr = s2re[(t + 128) * S2R + uu], Hi = s2im[(t + 128) * S2R + uu];
        re[2*uu]     = pklo(Lr, Hr);  im[2*uu]     = pklo(Li, Hi);
        re[2*uu + 1] = pkhi(Lr, Hr);  im[2*uu + 1] = pkhi(Li, Hi);
    }
    fft16_nat_p<-1>(re, im);     // over b2; F[256*d2 + r] at slot REV(d2)

    // ---- D scale (1/N folded), freq = 256*d2 + (t | t+128) ----
    #pragma unroll
    for (int d2 = 0; d2 < 16; ++d2){
        const float2 da = D2[256 * d2 + t];
        const float2 db = D2[256 * d2 + t + 128];
        const int s = REV(d2);
        re[s] = pmul(re[s], pk(da.x * INV_N, db.x * INV_N));
        im[s] = pmul(im[s], pk(da.y * INV_N, db.y * INV_N));
    }
    __syncthreads();

    // ================= inverse =================
    fft16_rev_p<1>(re, im);      // logical d2 at REV slot -> natural out
    twiddle_stage_p<1, 0>(re, im, (float)t * D4096, (float)(t + 128) * D4096);
    #pragma unroll
    for (int c = 0; c < 16; ++c){
        s1re[c * S1R + t] = re[c];   // pair = (r=t, r=t+128) at column t
        s1im[c * S1R + t] = im[c];
    }
    __syncthreads();
    // stage 2 inv: lanes = (b2 = u, u+8); stored pairs along a2 -> repack
    #pragma unroll
    for (int aa = 0; aa < 8; ++aa){
        const ull Lr = s1re[c1 * S1R + 16 * aa + u],     Li = s1im[c1 * S1R + 16 * aa + u];
        const ull Hr = s1re[c1 * S1R + 16 * aa + u + 8], Hi = s1im[c1 * S1R + 16 * aa + u + 8];
        re[aa]     = pklo(Lr, Hr);  im[aa]     = pklo(Li, Hi);
        re[aa + 8] = pkhi(Lr, Hr);  im[aa + 8] = pkhi(Li, Hi);
    }
    fft16_nat_p<1>(re, im);
    twiddle_stage_p<1, 1>(re, im, (float)u * D256, (float)(u + 8) * D256);
    __syncthreads();
    #pragma unroll
    for (int c2 = 0; c2 < 16; ++c2){
        const int r2 = 16 * c2 + c1;
        s2re[r2 * S2R + u] = re[REV(c2)];   // pair = (b2=u, u+8) at column u
        s2im[r2 * S2R + u] = im[REV(c2)];
    }
    __syncthreads();
    // stage 3 inv: lanes = (m = t, t+128); stored pairs along b2 -> repack
    #pragma unroll
    for (int uu = 0; uu < 8; ++uu){
        const ull Lr = s2re[t * S2R + uu],         Li = s2im[t * S2R + uu];
        const ull Hr = s2re[(t + 128) * S2R + uu], Hi = s2im[(t + 128) * S2R + uu];
        re[uu]     = pklo(Lr, Hr);  im[uu]     = pklo(Li, Hi);
        re[uu + 8] = pkhi(Lr, Hr);  im[uu + 8] = pkhi(Li, Hi);
    }
    fft16_nat_p<1>(re, im);      // over b2; out[256*d2 + m] at slot REV(d2)

    // ---- store ----
    #pragma unroll
    for (int d2 = 0; d2 < 16; ++d2){
        const int s = REV(d2);
        float r0, r1, i0, i1;
        unpk(re[s], r0, r1);
        unpk(im[s], i0, i1);
        out2[rb2 + 256 * d2 + t]       = make_float2(r0, i0);
        out2[rb2 + 256 * d2 + t + 128] = make_float2(r1, i1);
    }
}

extern "C" void kernel_launch(void* const* d_in, const int* in_sizes, int n_in,
                              void* d_out, int out_size)
{
    const float4* x4 = (const float4*)d_in[0];
    const float4* A4 = (const float4*)d_in[1];
    const float2* D2 = (const float2*)d_in[2];
    float2* out2 = (float2*)d_out;

    const int rows = in_sizes[0] / (4096 * 2);
    afdf_fft2_kernel<<<rows, 128>>>(x4, A4, D2, out2);
}